// round 13
// baseline (speedup 1.0000x reference)
#include <cuda_runtime.h>
#include <cuda_fp16.h>
#include <math.h>
#include <stdint.h>

// Problem dims
#define BB 2
#define LL 2048
#define DD 1024
#define VV 32000
#define NLAYERS 2
#define EE 2048
#define NN_ 16
#define RR 64
#define KK 4
#define NTOK (BB*LL)          // 4096 tokens

// ---------------- scratch (device globals; no allocation allowed) ----------
__device__ float  g_x   [NTOK*DD];      // residual fp32
__device__ __half g_xn  [NTOK*DD];      // rmsnorm out fp16
__device__ float  g_xz  [NTOK*2*EE];    // W_in out fp32
__device__ __half g_xc  [NTOK*EE];      // conv+silu out fp16 [t][e]
__device__ __half g_xcT [EE*NTOK];      // conv+silu out fp16 [e][t]
__device__ __half g_gT  [EE*NTOK];      // silu(z) fp16 [e][t]
__device__ __half g_dblh[NTOK*96];      // xproj out hi fp16 (dt GEMM B)
__device__ __half g_dbll[NTOK*96];      // xproj out lo fp16
__device__ float  g_bcT [32*NTOK];      // B (rows 0..15), C (rows 16..31) [n][tk]
__device__ float  g_xpart[4*NTOK*96];   // xproj split-K partials
__device__ float  g_dtT [EE*NTOK];      // softplus(dt) fp32 [e][tk]
__device__ __half g_y   [NTOK*EE];      // scan out fp16 [t][e]
// fp16 hi/lo split weight buffers (sized for lm_head: 32000x1024)
__device__ __half g_bh[VV*DD];
__device__ __half g_bl[VV*DD];

// ======================= helpers ==============================
__device__ __forceinline__ uint32_t smem_u32(const void* p) {
    uint32_t a;
    asm("{ .reg .u64 t; cvta.to.shared.u64 t, %1; cvt.u32.u64 %0, t; }" : "=r"(a) : "l"(p));
    return a;
}
// SW64 swizzle for 64-byte rows (Swizzle<2,4,3>)
#define SWZ64(off) ((off) ^ (((off) >> 3) & 0x30))

__device__ __forceinline__ void ldsm4(uint32_t addr, uint32_t* r) {
    asm volatile("ldmatrix.sync.aligned.m8n8.x4.shared.b16 {%0,%1,%2,%3}, [%4];"
                 : "=r"(r[0]), "=r"(r[1]), "=r"(r[2]), "=r"(r[3]) : "r"(addr));
}
__device__ __forceinline__ void mma_f16(float* d, const uint32_t* a, uint32_t b0, uint32_t b1) {
    asm volatile(
        "mma.sync.aligned.m16n8k16.row.col.f32.f16.f16.f32 "
        "{%0,%1,%2,%3}, {%4,%5,%6,%7}, {%8,%9}, {%0,%1,%2,%3};"
        : "+f"(d[0]), "+f"(d[1]), "+f"(d[2]), "+f"(d[3])
        : "r"(a[0]), "r"(a[1]), "r"(a[2]), "r"(a[3]), "r"(b0), "r"(b1));
}
__device__ __forceinline__ void cp16(uint32_t s, const void* g, bool p) {
    asm volatile("cp.async.cg.shared.global [%0], [%1], 16, %2;"
                 :: "r"(s), "l"(g), "r"(p ? 16 : 0) : "memory");
}
#define CP_COMMIT() asm volatile("cp.async.commit_group;" ::: "memory")

__device__ __forceinline__ float softplus_f(float v) {
    return (v > 20.f) ? v : log1pf(expf(v));
}
__device__ __forceinline__ float h2f_lo(uint32_t w) {
    return __half2float(__ushort_as_half((unsigned short)(w & 0xFFFFu)));
}
__device__ __forceinline__ float h2f_hi(uint32_t w) {
    return __half2float(__ushort_as_half((unsigned short)(w >> 16)));
}

// ======================= fp16 mma.sync GEMM ==================================
// K-chunk 32, SW64 rows. NT=1: 6-stage ring, stage 16KB (AH 8K + BH 8K).
//                        NT=2: 4-stage ring, stage 24KB (AH/BH/BL 8K each).
// A fp16 row-major (lda), Bh/Bl fp16 [N,K] K-major (ldb).
// CTA tile 128x128, 8 warps (4m x 2n, warp tile 32x64).
// grid: (M/128, ceil(N/128), ksplit)
// EPI: 0=store fp32, 1=C+=acc, 3=softplus(acc+bias[row])
template<int EPI, int NT>
__global__ __launch_bounds__(256, 2)
void mmagemm(const __half* __restrict__ Ah,
             const __half* __restrict__ Bh, const __half* __restrict__ Bl,
             float* __restrict__ C, const float* __restrict__ bias,
             int N, int K, int lda, int ldb, int ldc, size_t czstride)
{
    constexpr int      STAGES = (NT == 1) ? 6 : 4;
    constexpr uint32_t STAGE  = (NT == 1) ? 16384u : 24576u;
    constexpr uint32_t OFF_BH = 8192u;
    constexpr uint32_t OFF_BL = 16384u;   // NT2 only

    extern __shared__ __align__(1024) char smem[];
    uint32_t sb = smem_u32(smem);
    const int tid = threadIdx.x;
    const int lane = tid & 31;
    const int wid = tid >> 5;
    const int warp_m = wid >> 1;
    const int warp_n = wid & 1;
    const int bm = blockIdx.x * 128;
    const int bn = blockIdx.y * 128;
    const int zoff = blockIdx.z * K;
    float* Cz = C + (size_t)blockIdx.z * czstride;
    const int nch = K >> 5;

    float acc[2][8][4];
    #pragma unroll
    for (int i = 0; i < 2; i++)
        #pragma unroll
        for (int j = 0; j < 8; j++)
            #pragma unroll
            for (int q = 0; q < 4; q++) acc[i][j][q] = 0.f;

    auto issue = [&](int c, int s) {
        if (c >= nch) return;
        uint32_t st = sb + (uint32_t)s * STAGE;
        const int k0 = zoff + (c << 5);
        const __half* pAh = Ah + (size_t)bm * lda + k0;
        #pragma unroll
        for (int i = 0; i < 2; i++) {           // 128 rows x 4 chunks of 16B
            int idx = i * 256 + tid;
            int row = idx >> 2, c4 = idx & 3;
            uint32_t so = SWZ64((uint32_t)(row * 64 + c4 * 16));
            cp16(st + so, pAh + (size_t)row * lda + c4 * 8, true);
        }
        const __half* pBh = Bh + k0;
        #pragma unroll
        for (int i = 0; i < 2; i++) {
            int idx = i * 256 + tid;
            int row = idx >> 2, c4 = idx & 3;
            bool ok = (bn + row) < N;
            size_t gr = ok ? (size_t)(bn + row) : 0;
            uint32_t so = SWZ64((uint32_t)(row * 64 + c4 * 16));
            cp16(st + OFF_BH + so, pBh + gr * ldb + c4 * 8, ok);
        }
        if (NT == 2) {
            const __half* pBl = Bl + k0;
            #pragma unroll
            for (int i = 0; i < 2; i++) {
                int idx = i * 256 + tid;
                int row = idx >> 2, c4 = idx & 3;
                bool ok = (bn + row) < N;
                size_t gr = ok ? (size_t)(bn + row) : 0;
                uint32_t so = SWZ64((uint32_t)(row * 64 + c4 * 16));
                cp16(st + OFF_BL + so, pBl + gr * ldb + c4 * 8, ok);
            }
        }
    };

    #pragma unroll
    for (int s = 0; s < STAGES - 1; s++) { issue(s, s); CP_COMMIT(); }

    const int arow_l  = warp_m * 32 + (lane & 15);
    const int akoff_l = (lane >> 4) << 4;
    const int brow_l  = warp_n * 64 + (lane & 7) + ((lane >> 4) << 3);
    const int bkoff_l = ((lane >> 3) & 1) << 4;

    for (int c = 0; c < nch; c++) {
        asm volatile("cp.async.wait_group %0;" :: "n"(STAGES - 2) : "memory");
        __syncthreads();
        uint32_t base = sb + (uint32_t)((c % STAGES) * STAGE);
        #pragma unroll
        for (int ks = 0; ks < 2; ks++) {
            const int kb = ks * 32;
            uint32_t ah[2][4];
            #pragma unroll
            for (int mi = 0; mi < 2; mi++) {
                uint32_t off = SWZ64((uint32_t)((arow_l + mi * 16) * 64 + kb + akoff_l));
                ldsm4(base + off, ah[mi]);
            }
            #pragma unroll
            for (int nj2 = 0; nj2 < 4; nj2++) {
                uint32_t bh[4], bl[4];
                uint32_t off = SWZ64((uint32_t)((brow_l + nj2 * 16) * 64 + kb + bkoff_l));
                ldsm4(base + OFF_BH + off, bh);
                if (NT == 2) ldsm4(base + OFF_BL + off, bl);
                #pragma unroll
                for (int mi = 0; mi < 2; mi++) {
                    mma_f16(acc[mi][nj2*2+0], ah[mi], bh[0], bh[1]);
                    mma_f16(acc[mi][nj2*2+1], ah[mi], bh[2], bh[3]);
                    if (NT == 2) {
                        mma_f16(acc[mi][nj2*2+0], ah[mi], bl[0], bl[1]);
                        mma_f16(acc[mi][nj2*2+1], ah[mi], bl[2], bl[3]);
                    }
                }
            }
        }
        // writes slot (c+STAGES-1)%STAGES == (c-1)%STAGES — all warps finished
        // reading it before the __syncthreads() at the top of this iteration.
        issue(c + STAGES - 1, (c + STAGES - 1) % STAGES);
        CP_COMMIT();
    }

    // ---- epilogue ----
    #pragma unroll
    for (int mi = 0; mi < 2; mi++) {
        #pragma unroll
        for (int nj = 0; nj < 8; nj++) {
            int row = bm + warp_m * 32 + mi * 16 + (lane >> 2);
            int col = bn + warp_n * 64 + nj * 8 + (lane & 3) * 2;
            if (col < N) {
                float* d = acc[mi][nj];
                float2 v0 = make_float2(d[0], d[1]);
                float2 v1 = make_float2(d[2], d[3]);
                float* p0 = Cz + (size_t)row * ldc + col;
                float* p1 = Cz + (size_t)(row + 8) * ldc + col;
                if (EPI == 1) {
                    float2 o0 = *(float2*)p0; v0.x += o0.x; v0.y += o0.y;
                    float2 o1 = *(float2*)p1; v1.x += o1.x; v1.y += o1.y;
                } else if (EPI == 3) {
                    float br0 = bias[row], br1 = bias[row + 8];
                    v0.x = softplus_f(v0.x + br0); v0.y = softplus_f(v0.y + br0);
                    v1.x = softplus_f(v1.x + br1); v1.y = softplus_f(v1.y + br1);
                }
                *(float2*)p0 = v0;
                *(float2*)p1 = v1;
            }
        }
    }
}

// ============== weight prep: fp32 (K,N) -> fp16 hi (+optional lo) [N,K] =====
__global__ void transpose_split_f16(const float* __restrict__ W, int K, int N,
                                    __half* __restrict__ Bh, __half* __restrict__ Bl)
{
    __shared__ float t[32][33];
    int k0 = blockIdx.x * 32, n0 = blockIdx.y * 32;
    int tx = threadIdx.x, ty = threadIdx.y;   // 32 x 8
    #pragma unroll
    for (int i = 0; i < 4; i++) {
        int k = k0 + ty + 8 * i;
        float v = (n0 + tx < N) ? W[(size_t)k * N + n0 + tx] : 0.f;
        t[ty + 8 * i][tx] = v;
    }
    __syncthreads();
    #pragma unroll
    for (int i = 0; i < 4; i++) {
        int n = n0 + ty + 8 * i;
        int k = k0 + tx;
        float v = t[tx][ty + 8 * i];
        __half h = __float2half_rn(v);
        Bh[(size_t)n * K + k] = h;
        if (Bl) Bl[(size_t)n * K + k] = __float2half_rn(v - __half2float(h));
    }
}

// elementwise fp32 -> fp16 cast (already [N,K] layout): lm_head, hi only
__global__ void cast_f16(const float4* __restrict__ W,
                         __half* __restrict__ Bh, int n4)
{
    int i = blockIdx.x * blockDim.x + threadIdx.x;
    if (i >= n4) return;
    float4 v = W[i];
    __half2 h0 = __floats2half2_rn(v.x, v.y);
    __half2 h1 = __floats2half2_rn(v.z, v.w);
    uint2 hh;
    hh.x = *(uint32_t*)&h0;  hh.y = *(uint32_t*)&h1;
    ((uint2*)Bh)[i] = hh;
}

// ---------------- xproj split-K reduce: dbl hi/lo + transposed B,C ---------
__global__ void reduce_xproj()
{
    int i = blockIdx.x * blockDim.x + threadIdx.x;
    if (i >= NTOK * 96) return;
    float s = g_xpart[i] + g_xpart[i + NTOK*96] + g_xpart[i + 2*NTOK*96] + g_xpart[i + 3*NTOK*96];
    int c = i % 96, t = i / 96;
    if (c < 64) {
        __half h = __float2half_rn(s);
        __half l = __float2half_rn(s - __half2float(h));
        g_dblh[i] = h;
        g_dbll[i] = l;
    } else {
        g_bcT[(size_t)(c - 64) * NTOK + t] = s;
    }
}

// ---------------- embed gather ----------------
__global__ void embed_kernel(const int* __restrict__ tokens,
                             const float* __restrict__ embed)
{
    int t = blockIdx.x;
    int tok = tokens[t];
    const float4* src = (const float4*)(embed + (size_t)tok * DD);
    float4* dst = (float4*)(g_x + (size_t)t * DD);
    for (int i = threadIdx.x; i < DD/4; i += blockDim.x)
        dst[i] = src[i];
}

// ---------------- rmsnorm (writes fp16) ----------------
__global__ void rmsnorm_kernel(const float* __restrict__ x,
                               const float* __restrict__ w,
                               __half* __restrict__ o)
{
    int t = blockIdx.x;
    const float4* xr = (const float4*)(x + (size_t)t * DD);
    const float4* wr = (const float4*)w;

    float s = 0.f;
    for (int i = threadIdx.x; i < DD/4; i += blockDim.x) {
        float4 v = xr[i];
        s += v.x*v.x + v.y*v.y + v.z*v.z + v.w*v.w;
    }
    __shared__ float red[8];
    for (int m = 16; m > 0; m >>= 1) s += __shfl_xor_sync(0xffffffffu, s, m);
    if ((threadIdx.x & 31) == 0) red[threadIdx.x >> 5] = s;
    __syncthreads();
    float tot = 0.f;
    if (threadIdx.x < 8) tot = red[threadIdx.x];
    for (int m = 4; m > 0; m >>= 1) tot += __shfl_xor_sync(0xffffffffu, tot, m);
    __shared__ float inv_s;
    if (threadIdx.x == 0) inv_s = rsqrtf(tot / (float)DD + 1e-5f);
    __syncthreads();
    float inv = inv_s;

    for (int i = threadIdx.x; i < DD/4; i += blockDim.x) {
        float4 v = xr[i];
        float4 wv = wr[i];
        __half2 h0 = __floats2half2_rn(v.x * wv.x * inv, v.y * wv.y * inv);
        __half2 h1 = __floats2half2_rn(v.z * wv.z * inv, v.w * wv.w * inv);
        uint2 hh;
        hh.x = *(uint32_t*)&h0; hh.y = *(uint32_t*)&h1;
        *(uint2*)(o + (size_t)t * DD + i * 4) = hh;
    }
}

// ------ fused causal conv (K=4) + silu + gate + dual-layout transpose ------
__global__ void conv_fused(const float* __restrict__ conv_w,
                           const float* __restrict__ conv_b)
{
    __shared__ __half tx[32][33];
    __shared__ __half tg[32][33];
    int t0 = blockIdx.x * 32, e0 = blockIdx.y * 32;
    int lx = threadIdx.x, ly = threadIdx.y;
    int e = e0 + lx;
    float w0 = conv_w[e*KK+0], w1 = conv_w[e*KK+1], w2 = conv_w[e*KK+2], w3 = conv_w[e*KK+3];
    float cb = conv_b[e];
    #pragma unroll
    for (int i = 0; i < 4; i++) {
        int tk = t0 + ly + 8 * i;
        int t = tk % LL;
        const float* src = g_xz + (size_t)(tk - t) * (2*EE) + e;
        float acc = cb;
        if (t >= 3) {
            acc = fmaf(w0, src[(size_t)(t-3)*(2*EE)], acc);
            acc = fmaf(w1, src[(size_t)(t-2)*(2*EE)], acc);
            acc = fmaf(w2, src[(size_t)(t-1)*(2*EE)], acc);
            acc = fmaf(w3, src[(size_t)(t  )*(2*EE)], acc);
        } else {
            if (t-3 >= 0) acc = fmaf(w0, src[(size_t)(t-3)*(2*EE)], acc);
            if (t-2 >= 0) acc = fmaf(w1, src[(size_t)(t-2)*(2*EE)], acc);
            if (t-1 >= 0) acc = fmaf(w2, src[(size_t)(t-1)*(2*EE)], acc);
            acc = fmaf(w3, src[(size_t)t*(2*EE)], acc);
        }
        float sg = 1.f / (1.f + __expf(-acc));
        float v = acc * sg;
        __half hv = __float2half_rn(v);
        g_xc[(size_t)tk * EE + e] = hv;
        tx[ly + 8 * i][lx] = hv;
        float z = g_xz[(size_t)tk * (2*EE) + EE + e];
        float zg = 1.f / (1.f + __expf(-z));
        tg[ly + 8 * i][lx] = __float2half_rn(z * zg);
    }
    __syncthreads();
    #pragma unroll
    for (int i = 0; i < 4; i++) {
        int ee = e0 + ly + 8 * i;
        g_xcT[(size_t)ee * NTOK + t0 + lx] = tx[lx][ly + 8 * i];
        g_gT [(size_t)ee * NTOK + t0 + lx] = tg[lx][ly + 8 * i];
    }
}

// ---------------- selective scan (transposed layout, vector prefetch) ------
#define SD 8
__global__ __launch_bounds__(128)
void scan_kernel(const float* __restrict__ A_log,
                 const float* __restrict__ D_skip)
{
    int group = threadIdx.x >> 4;
    int n     = threadIdx.x & 15;
    int ch    = blockIdx.x * 8 + group;   // 0..4095
    int b = ch >> 11;
    int e = ch & (EE - 1);

    float a   = -__expf(A_log[e * NN_ + n]);
    float dsk = D_skip[e];
    float h = 0.f;

    const float*  dtp = g_dtT + (size_t)e * NTOK + b * LL;
    const __half* xp  = g_xcT + (size_t)e * NTOK + b * LL;
    const __half* gp  = g_gT  + (size_t)e * NTOK + b * LL;
    const float*  Bp  = g_bcT + (size_t)n * NTOK + b * LL;
    const float*  Cp  = g_bcT + (size_t)(16 + n) * NTOK + b * LL;
    __half* y0 = g_y + (size_t)b * LL * EE + e;

    float p_dt[2][SD], p_B[2][SD], p_C[2][SD], p_x[2][SD], p_g[2][SD];

#define PREF(BK, TP) do {                                                    \
    int tb = (TP) > (LL - SD) ? (LL - SD) : (TP);                            \
    float4 v0 = *(const float4*)(dtp + tb);                                  \
    float4 v1 = *(const float4*)(dtp + tb + 4);                              \
    p_dt[BK][0]=v0.x; p_dt[BK][1]=v0.y; p_dt[BK][2]=v0.z; p_dt[BK][3]=v0.w;  \
    p_dt[BK][4]=v1.x; p_dt[BK][5]=v1.y; p_dt[BK][6]=v1.z; p_dt[BK][7]=v1.w;  \
    v0 = *(const float4*)(Bp + tb); v1 = *(const float4*)(Bp + tb + 4);      \
    p_B[BK][0]=v0.x; p_B[BK][1]=v0.y; p_B[BK][2]=v0.z; p_B[BK][3]=v0.w;      \
    p_B[BK][4]=v1.x; p_B[BK][5]=v1.y; p_B[BK][6]=v1.z; p_B[BK][7]=v1.w;      \
    v0 = *(const float4*)(Cp + tb); v1 = *(const float4*)(Cp + tb + 4);      \
    p_C[BK][0]=v0.x; p_C[BK][1]=v0.y; p_C[BK][2]=v0.z; p_C[BK][3]=v0.w;      \
    p_C[BK][4]=v1.x; p_C[BK][5]=v1.y; p_C[BK][6]=v1.z; p_C[BK][7]=v1.w;      \
    uint4 u = *(const uint4*)(xp + tb);                                      \
    p_x[BK][0]=h2f_lo(u.x); p_x[BK][1]=h2f_hi(u.x);                          \
    p_x[BK][2]=h2f_lo(u.y); p_x[BK][3]=h2f_hi(u.y);                          \
    p_x[BK][4]=h2f_lo(u.z); p_x[BK][5]=h2f_hi(u.z);                          \
    p_x[BK][6]=h2f_lo(u.w); p_x[BK][7]=h2f_hi(u.w);                          \
    u = *(const uint4*)(gp + tb);                                            \
    p_g[BK][0]=h2f_lo(u.x); p_g[BK][1]=h2f_hi(u.x);                          \
    p_g[BK][2]=h2f_lo(u.y); p_g[BK][3]=h2f_hi(u.y);                          \
    p_g[BK][4]=h2f_lo(u.z); p_g[BK][5]=h2f_hi(u.z);                          \
    p_g[BK][6]=h2f_lo(u.w); p_g[BK][7]=h2f_hi(u.w);                          \
} while (0)

#define COMP(BK, T0) do {                                                    \
    _Pragma("unroll")                                                        \
    for (int j = 0; j < SD; j++) {                                           \
        float dte = p_dt[BK][j];                                             \
        float xe  = p_x[BK][j];                                              \
        float dA  = __expf(dte * a);                                         \
        h = fmaf(h, dA, dte * xe * p_B[BK][j]);                              \
        float p = h * p_C[BK][j];                                            \
        p += __shfl_xor_sync(0xffffffffu, p, 8);                             \
        p += __shfl_xor_sync(0xffffffffu, p, 4);                             \
        p += __shfl_xor_sync(0xffffffffu, p, 2);                             \
        p += __shfl_xor_sync(0xffffffffu, p, 1);                             \
        if (n == 0) {                                                        \
            float y = (p + xe * dsk) * p_g[BK][j];                           \
            y0[(size_t)((T0) + j) * EE] = __float2half_rn(y);                \
        }                                                                    \
    } } while (0)

    PREF(0, 0);
    for (int t0 = 0; t0 < LL; t0 += 2*SD) {
        PREF(1, t0 + SD);
        COMP(0, t0);
        PREF(0, t0 + 2*SD);
        COMP(1, t0 + SD);
    }
#undef PREF
#undef COMP
}

// ---------------- host launch ----------------
extern "C" void kernel_launch(void* const* d_in, const int* in_sizes, int n_in,
                              void* d_out, int out_size)
{
    const int*   tokens   = (const int*)  d_in[0];
    const float* embed    = (const float*)d_in[1];
    const float* norm_w   = (const float*)d_in[2];
    const float* W_in     = (const float*)d_in[3];
    const float* conv_w   = (const float*)d_in[4];
    const float* conv_b   = (const float*)d_in[5];
    const float* W_xproj  = (const float*)d_in[6];
    const float* W_dt     = (const float*)d_in[7];
    const float* dt_bias  = (const float*)d_in[8];
    const float* A_log    = (const float*)d_in[9];
    const float* D_skip   = (const float*)d_in[10];
    const float* W_out    = (const float*)d_in[11];
    const float* final_nw = (const float*)d_in[12];
    const float* lm_head  = (const float*)d_in[13];
    float* out = (float*)d_out;

    float *px, *pxz, *pxpart, *pdtT;
    __half *pxn, *pxc, *pdblh, *pdbll, *py, *pbh, *pbl;
    cudaGetSymbolAddress((void**)&px,    g_x);
    cudaGetSymbolAddress((void**)&pxn,   g_xn);
    cudaGetSymbolAddress((void**)&pxz,   g_xz);
    cudaGetSymbolAddress((void**)&pxc,   g_xc);
    cudaGetSymbolAddress((void**)&pdblh, g_dblh);
    cudaGetSymbolAddress((void**)&pdbll, g_dbll);
    cudaGetSymbolAddress((void**)&pdtT,  g_dtT);
    cudaGetSymbolAddress((void**)&py,    g_y);
    cudaGetSymbolAddress((void**)&pbh,   g_bh);
    cudaGetSymbolAddress((void**)&pbl,   g_bl);
    cudaGetSymbolAddress((void**)&pxpart, g_xpart);

    static bool attr_done = false;
    if (!attr_done) {
        cudaFuncSetAttribute(mmagemm<3,2>, cudaFuncAttributeMaxDynamicSharedMemorySize, 4*24576);
        cudaFuncSetAttribute(mmagemm<0,1>, cudaFuncAttributeMaxDynamicSharedMemorySize, 6*16384);
        cudaFuncSetAttribute(mmagemm<1,1>, cudaFuncAttributeMaxDynamicSharedMemorySize, 6*16384);
        attr_done = true;
    }

    embed_kernel<<<NTOK, 256>>>(tokens, embed);

    for (int l = 0; l < NLAYERS; l++) {
        const float* nw  = norm_w  + (size_t)l * DD;
        const float* win = W_in    + (size_t)l * DD * 2 * EE;
        const float* cw  = conv_w  + (size_t)l * EE * KK;
        const float* cb  = conv_b  + (size_t)l * EE;
        const float* wxp = W_xproj + (size_t)l * EE * 96;
        const float* wdt = W_dt    + (size_t)l * RR * EE;
        const float* dtb = dt_bias + (size_t)l * EE;
        const float* alg = A_log   + (size_t)l * EE * NN_;
        const float* dsk = D_skip  + (size_t)l * EE;
        const float* wo  = W_out   + (size_t)l * EE * DD;

        // 1. rmsnorm -> fp16 xn
        rmsnorm_kernel<<<NTOK, 256>>>(px, nw, pxn);

        // 2. xz = xn @ W_in   (1-term fp16)
        transpose_split_f16<<<dim3(DD/32, (2*EE)/32), dim3(32,8)>>>(win, DD, 2*EE, pbh, nullptr);
        mmagemm<0,1><<<dim3(NTOK/128, (2*EE)/128), 256, 6*16384>>>(
            pxn, pbh, nullptr, pxz, nullptr,
            2*EE, DD, DD, DD, 2*EE, 0);

        // 3. fused conv + silu + gate + transposes
        conv_fused<<<dim3(NTOK/32, EE/32), dim3(32,8)>>>(cw, cb);

        // 4. dbl = xc @ W_xproj  (1-term), split-K x4 + reduce
        transpose_split_f16<<<dim3(EE/32, 128/32), dim3(32,8)>>>(wxp, EE, 96, pbh, nullptr);
        mmagemm<0,1><<<dim3(NTOK/128, 1, 4), 256, 6*16384>>>(
            pxc, pbh, nullptr, pxpart, nullptr,
            96, EE/4, EE, EE, 96, (size_t)NTOK*96);
        reduce_xproj<<<(NTOK*96 + 255)/256, 256>>>();

        // 5. dtT = softplus(W_dt^T @ dbl^T + bias[row]) (2-term) -> [E, NTOK]
        transpose_split_f16<<<dim3(RR/32, EE/32), dim3(32,8)>>>(wdt, RR, EE, pbh, pbl);
        mmagemm<3,2><<<dim3(EE/128, NTOK/128), 256, 4*24576>>>(
            pbh, pdblh, pdbll, pdtT, dtb,
            NTOK, RR, RR, 96, NTOK, 0);

        // 6. selective scan + gate -> fp16 y [t][e]
        scan_kernel<<<(BB*EE)/8, 128>>>(alg, dsk);

        // 7. x += y @ W_out  (1-term fp16)
        transpose_split_f16<<<dim3(EE/32, DD/32), dim3(32,8)>>>(wo, EE, DD, pbh, nullptr);
        mmagemm<1,1><<<dim3(NTOK/128, DD/128), 256, 6*16384>>>(
            py, pbh, nullptr, px, nullptr,
            DD, EE, EE, EE, DD, 0);
    }

    // final rmsnorm -> fp16 xn
    rmsnorm_kernel<<<NTOK, 256>>>(px, final_nw, pxn);

    // logits = xn @ lm_head^T  (1-term fp16); lm_head already [N,K]
    cast_f16<<<(VV*DD/4 + 255)/256, 256>>>((const float4*)lm_head, pbh, VV*DD/4);
    mmagemm<0,1><<<dim3(NTOK/128, VV/128), 256, 6*16384>>>(
        pxn, pbh, nullptr, out, nullptr,
        VV, DD, DD, DD, VV, 0);
}

// round 14
// speedup vs baseline: 1.0487x; 1.0487x over previous
#include <cuda_runtime.h>
#include <cuda_fp16.h>
#include <math.h>
#include <stdint.h>

// Problem dims
#define BB 2
#define LL 2048
#define DD 1024
#define VV 32000
#define NLAYERS 2
#define EE 2048
#define NN_ 16
#define RR 64
#define KK 4
#define NTOK (BB*LL)          // 4096 tokens

// ---------------- scratch (device globals; no allocation allowed) ----------
__device__ float  g_x   [NTOK*DD];      // residual fp32
__device__ __half g_xn  [NTOK*DD];      // rmsnorm out fp16
__device__ float  g_xz  [NTOK*2*EE];    // W_in out fp32
__device__ __half g_xc  [NTOK*EE];      // conv+silu out fp16 [t][e]
__device__ __half g_xcT [EE*NTOK];      // conv+silu out fp16 [e][t]
__device__ __half g_gT  [EE*NTOK];      // silu(z) fp16 [e][t]
__device__ __half g_dblh[NTOK*96];      // xproj out hi fp16 (dt GEMM B)
__device__ __half g_dbll[NTOK*96];      // xproj out lo fp16
__device__ float  g_bcT [32*NTOK];      // B (rows 0..15), C (rows 16..31) [n][tk]
__device__ float  g_xpart[4*NTOK*96];   // xproj split-K partials
__device__ float  g_dtT [EE*NTOK];      // softplus(dt) fp32 [e][tk]
__device__ __half g_y   [NTOK*EE];      // scan out fp16 [t][e]
// fp16 hi/lo split weight buffers (sized for lm_head: 32000x1024)
__device__ __half g_bh[VV*DD];
__device__ __half g_bl[VV*DD];

// ======================= helpers ==============================
__device__ __forceinline__ uint32_t smem_u32(const void* p) {
    uint32_t a;
    asm("{ .reg .u64 t; cvta.to.shared.u64 t, %1; cvt.u32.u64 %0, t; }" : "=r"(a) : "l"(p));
    return a;
}
// SW64 swizzle for 64-byte rows (Swizzle<2,4,3>)
#define SWZ64(off) ((off) ^ (((off) >> 3) & 0x30))

__device__ __forceinline__ void ldsm4(uint32_t addr, uint32_t* r) {
    asm volatile("ldmatrix.sync.aligned.m8n8.x4.shared.b16 {%0,%1,%2,%3}, [%4];"
                 : "=r"(r[0]), "=r"(r[1]), "=r"(r[2]), "=r"(r[3]) : "r"(addr));
}
__device__ __forceinline__ void mma_f16(float* d, const uint32_t* a, uint32_t b0, uint32_t b1) {
    asm volatile(
        "mma.sync.aligned.m16n8k16.row.col.f32.f16.f16.f32 "
        "{%0,%1,%2,%3}, {%4,%5,%6,%7}, {%8,%9}, {%0,%1,%2,%3};"
        : "+f"(d[0]), "+f"(d[1]), "+f"(d[2]), "+f"(d[3])
        : "r"(a[0]), "r"(a[1]), "r"(a[2]), "r"(a[3]), "r"(b0), "r"(b1));
}
__device__ __forceinline__ void cp16(uint32_t s, const void* g, bool p) {
    asm volatile("cp.async.cg.shared.global [%0], [%1], 16, %2;"
                 :: "r"(s), "l"(g), "r"(p ? 16 : 0) : "memory");
}
#define CP_COMMIT() asm volatile("cp.async.commit_group;" ::: "memory")
#define CP_WAIT2()  asm volatile("cp.async.wait_group 2;"  ::: "memory")

__device__ __forceinline__ float softplus_f(float v) {
    return (v > 20.f) ? v : log1pf(expf(v));
}
__device__ __forceinline__ float h2f_lo(uint32_t w) {
    return __half2float(__ushort_as_half((unsigned short)(w & 0xFFFFu)));
}
__device__ __forceinline__ float h2f_hi(uint32_t w) {
    return __half2float(__ushort_as_half((unsigned short)(w >> 16)));
}

// ======================= fp16 mma.sync GEMM (R11 config: 4-stage, wait 2) ===
// K-chunk 32, SW64 rows. NT=1: stage 16KB (AH 8K + BH 8K).
//                        NT=2: stage 24KB (AH/BH/BL 8K each).
// A fp16 row-major (lda), Bh/Bl fp16 [N,K] K-major (ldb).
// CTA tile 128x128, 8 warps (4m x 2n, warp tile 32x64).
// grid: (M/128, ceil(N/128), ksplit)
// EPI: 0=store fp32, 1=C+=acc, 3=softplus(acc+bias[row])
template<int EPI, int NT>
__global__ __launch_bounds__(256, 2)
void mmagemm(const __half* __restrict__ Ah,
             const __half* __restrict__ Bh, const __half* __restrict__ Bl,
             float* __restrict__ C, const float* __restrict__ bias,
             int N, int K, int lda, int ldb, int ldc, size_t czstride)
{
    constexpr uint32_t STAGE  = (NT == 1) ? 16384u : 24576u;
    constexpr uint32_t OFF_BH = 8192u;
    constexpr uint32_t OFF_BL = 16384u;   // NT2 only

    extern __shared__ __align__(1024) char smem[];
    uint32_t sb = smem_u32(smem);
    const int tid = threadIdx.x;
    const int lane = tid & 31;
    const int wid = tid >> 5;
    const int warp_m = wid >> 1;
    const int warp_n = wid & 1;
    const int bm = blockIdx.x * 128;
    const int bn = blockIdx.y * 128;
    const int zoff = blockIdx.z * K;
    float* Cz = C + (size_t)blockIdx.z * czstride;
    const int nch = K >> 5;

    float acc[2][8][4];
    #pragma unroll
    for (int i = 0; i < 2; i++)
        #pragma unroll
        for (int j = 0; j < 8; j++)
            #pragma unroll
            for (int q = 0; q < 4; q++) acc[i][j][q] = 0.f;

    auto issue = [&](int c, int s) {
        if (c >= nch) return;
        uint32_t st = sb + (uint32_t)s * STAGE;
        const int k0 = zoff + (c << 5);
        const __half* pAh = Ah + (size_t)bm * lda + k0;
        #pragma unroll
        for (int i = 0; i < 2; i++) {           // 128 rows x 4 chunks of 16B
            int idx = i * 256 + tid;
            int row = idx >> 2, c4 = idx & 3;
            uint32_t so = SWZ64((uint32_t)(row * 64 + c4 * 16));
            cp16(st + so, pAh + (size_t)row * lda + c4 * 8, true);
        }
        const __half* pBh = Bh + k0;
        #pragma unroll
        for (int i = 0; i < 2; i++) {
            int idx = i * 256 + tid;
            int row = idx >> 2, c4 = idx & 3;
            bool ok = (bn + row) < N;
            size_t gr = ok ? (size_t)(bn + row) : 0;
            uint32_t so = SWZ64((uint32_t)(row * 64 + c4 * 16));
            cp16(st + OFF_BH + so, pBh + gr * ldb + c4 * 8, ok);
        }
        if (NT == 2) {
            const __half* pBl = Bl + k0;
            #pragma unroll
            for (int i = 0; i < 2; i++) {
                int idx = i * 256 + tid;
                int row = idx >> 2, c4 = idx & 3;
                bool ok = (bn + row) < N;
                size_t gr = ok ? (size_t)(bn + row) : 0;
                uint32_t so = SWZ64((uint32_t)(row * 64 + c4 * 16));
                cp16(st + OFF_BL + so, pBl + gr * ldb + c4 * 8, ok);
            }
        }
    };

    issue(0, 0); CP_COMMIT();
    issue(1, 1); CP_COMMIT();
    issue(2, 2); CP_COMMIT();

    const int arow_l  = warp_m * 32 + (lane & 15);
    const int akoff_l = (lane >> 4) << 4;
    const int brow_l  = warp_n * 64 + (lane & 7) + ((lane >> 4) << 3);
    const int bkoff_l = ((lane >> 3) & 1) << 4;

    for (int c = 0; c < nch; c++) {
        CP_WAIT2();
        __syncthreads();
        uint32_t base = sb + (uint32_t)((c & 3) * STAGE);
        #pragma unroll
        for (int ks = 0; ks < 2; ks++) {
            const int kb = ks * 32;
            uint32_t ah[2][4];
            #pragma unroll
            for (int mi = 0; mi < 2; mi++) {
                uint32_t off = SWZ64((uint32_t)((arow_l + mi * 16) * 64 + kb + akoff_l));
                ldsm4(base + off, ah[mi]);
            }
            #pragma unroll
            for (int nj2 = 0; nj2 < 4; nj2++) {
                uint32_t bh[4], bl[4];
                uint32_t off = SWZ64((uint32_t)((brow_l + nj2 * 16) * 64 + kb + bkoff_l));
                ldsm4(base + OFF_BH + off, bh);
                if (NT == 2) ldsm4(base + OFF_BL + off, bl);
                #pragma unroll
                for (int mi = 0; mi < 2; mi++) {
                    mma_f16(acc[mi][nj2*2+0], ah[mi], bh[0], bh[1]);
                    mma_f16(acc[mi][nj2*2+1], ah[mi], bh[2], bh[3]);
                    if (NT == 2) {
                        mma_f16(acc[mi][nj2*2+0], ah[mi], bl[0], bl[1]);
                        mma_f16(acc[mi][nj2*2+1], ah[mi], bl[2], bl[3]);
                    }
                }
            }
        }
        // writes slot (c+3)&3 == (c-1)&3 — finished by all warps before the
        // sync at the top of this iteration.
        issue(c + 3, (c + 3) & 3);
        CP_COMMIT();
    }

    // ---- epilogue ----
    #pragma unroll
    for (int mi = 0; mi < 2; mi++) {
        #pragma unroll
        for (int nj = 0; nj < 8; nj++) {
            int row = bm + warp_m * 32 + mi * 16 + (lane >> 2);
            int col = bn + warp_n * 64 + nj * 8 + (lane & 3) * 2;
            if (col < N) {
                float* d = acc[mi][nj];
                float2 v0 = make_float2(d[0], d[1]);
                float2 v1 = make_float2(d[2], d[3]);
                float* p0 = Cz + (size_t)row * ldc + col;
                float* p1 = Cz + (size_t)(row + 8) * ldc + col;
                if (EPI == 1) {
                    float2 o0 = *(float2*)p0; v0.x += o0.x; v0.y += o0.y;
                    float2 o1 = *(float2*)p1; v1.x += o1.x; v1.y += o1.y;
                } else if (EPI == 3) {
                    float br0 = bias[row], br1 = bias[row + 8];
                    v0.x = softplus_f(v0.x + br0); v0.y = softplus_f(v0.y + br0);
                    v1.x = softplus_f(v1.x + br1); v1.y = softplus_f(v1.y + br1);
                }
                *(float2*)p0 = v0;
                *(float2*)p1 = v1;
            }
        }
    }
}

// ============== weight prep: fp32 (K,N) -> fp16 hi (+optional lo) [N,K] =====
__global__ void transpose_split_f16(const float* __restrict__ W, int K, int N,
                                    __half* __restrict__ Bh, __half* __restrict__ Bl)
{
    __shared__ float t[32][33];
    int k0 = blockIdx.x * 32, n0 = blockIdx.y * 32;
    int tx = threadIdx.x, ty = threadIdx.y;   // 32 x 8
    #pragma unroll
    for (int i = 0; i < 4; i++) {
        int k = k0 + ty + 8 * i;
        float v = (n0 + tx < N) ? W[(size_t)k * N + n0 + tx] : 0.f;
        t[ty + 8 * i][tx] = v;
    }
    __syncthreads();
    #pragma unroll
    for (int i = 0; i < 4; i++) {
        int n = n0 + ty + 8 * i;
        int k = k0 + tx;
        float v = t[tx][ty + 8 * i];
        __half h = __float2half_rn(v);
        Bh[(size_t)n * K + k] = h;
        if (Bl) Bl[(size_t)n * K + k] = __float2half_rn(v - __half2float(h));
    }
}

// elementwise fp32 -> fp16 cast (already [N,K] layout): lm_head, hi only
__global__ void cast_f16(const float4* __restrict__ W,
                         __half* __restrict__ Bh, int n4)
{
    int i = blockIdx.x * blockDim.x + threadIdx.x;
    if (i >= n4) return;
    float4 v = W[i];
    __half2 h0 = __floats2half2_rn(v.x, v.y);
    __half2 h1 = __floats2half2_rn(v.z, v.w);
    uint2 hh;
    hh.x = *(uint32_t*)&h0;  hh.y = *(uint32_t*)&h1;
    ((uint2*)Bh)[i] = hh;
}

// ---------------- xproj split-K reduce: dbl hi/lo + transposed B,C ---------
__global__ void reduce_xproj()
{
    int i = blockIdx.x * blockDim.x + threadIdx.x;
    if (i >= NTOK * 96) return;
    float s = g_xpart[i] + g_xpart[i + NTOK*96] + g_xpart[i + 2*NTOK*96] + g_xpart[i + 3*NTOK*96];
    int c = i % 96, t = i / 96;
    if (c < 64) {
        __half h = __float2half_rn(s);
        __half l = __float2half_rn(s - __half2float(h));
        g_dblh[i] = h;
        g_dbll[i] = l;
    } else {
        g_bcT[(size_t)(c - 64) * NTOK + t] = s;
    }
}

// ---------------- embed gather ----------------
__global__ void embed_kernel(const int* __restrict__ tokens,
                             const float* __restrict__ embed)
{
    int t = blockIdx.x;
    int tok = tokens[t];
    const float4* src = (const float4*)(embed + (size_t)tok * DD);
    float4* dst = (float4*)(g_x + (size_t)t * DD);
    for (int i = threadIdx.x; i < DD/4; i += blockDim.x)
        dst[i] = src[i];
}

// ---------------- rmsnorm (writes fp16) ----------------
__global__ void rmsnorm_kernel(const float* __restrict__ x,
                               const float* __restrict__ w,
                               __half* __restrict__ o)
{
    int t = blockIdx.x;
    const float4* xr = (const float4*)(x + (size_t)t * DD);
    const float4* wr = (const float4*)w;

    float s = 0.f;
    for (int i = threadIdx.x; i < DD/4; i += blockDim.x) {
        float4 v = xr[i];
        s += v.x*v.x + v.y*v.y + v.z*v.z + v.w*v.w;
    }
    __shared__ float red[8];
    for (int m = 16; m > 0; m >>= 1) s += __shfl_xor_sync(0xffffffffu, s, m);
    if ((threadIdx.x & 31) == 0) red[threadIdx.x >> 5] = s;
    __syncthreads();
    float tot = 0.f;
    if (threadIdx.x < 8) tot = red[threadIdx.x];
    for (int m = 4; m > 0; m >>= 1) tot += __shfl_xor_sync(0xffffffffu, tot, m);
    __shared__ float inv_s;
    if (threadIdx.x == 0) inv_s = rsqrtf(tot / (float)DD + 1e-5f);
    __syncthreads();
    float inv = inv_s;

    for (int i = threadIdx.x; i < DD/4; i += blockDim.x) {
        float4 v = xr[i];
        float4 wv = wr[i];
        __half2 h0 = __floats2half2_rn(v.x * wv.x * inv, v.y * wv.y * inv);
        __half2 h1 = __floats2half2_rn(v.z * wv.z * inv, v.w * wv.w * inv);
        uint2 hh;
        hh.x = *(uint32_t*)&h0; hh.y = *(uint32_t*)&h1;
        *(uint2*)(o + (size_t)t * DD + i * 4) = hh;
    }
}

// ------ fused causal conv (K=4) + silu + gate + dual-layout transpose ------
__global__ void conv_fused(const float* __restrict__ conv_w,
                           const float* __restrict__ conv_b)
{
    __shared__ __half tx[32][33];
    __shared__ __half tg[32][33];
    int t0 = blockIdx.x * 32, e0 = blockIdx.y * 32;
    int lx = threadIdx.x, ly = threadIdx.y;
    int e = e0 + lx;
    float w0 = conv_w[e*KK+0], w1 = conv_w[e*KK+1], w2 = conv_w[e*KK+2], w3 = conv_w[e*KK+3];
    float cb = conv_b[e];
    #pragma unroll
    for (int i = 0; i < 4; i++) {
        int tk = t0 + ly + 8 * i;
        int t = tk % LL;
        const float* src = g_xz + (size_t)(tk - t) * (2*EE) + e;
        float acc = cb;
        if (t >= 3) {
            acc = fmaf(w0, src[(size_t)(t-3)*(2*EE)], acc);
            acc = fmaf(w1, src[(size_t)(t-2)*(2*EE)], acc);
            acc = fmaf(w2, src[(size_t)(t-1)*(2*EE)], acc);
            acc = fmaf(w3, src[(size_t)(t  )*(2*EE)], acc);
        } else {
            if (t-3 >= 0) acc = fmaf(w0, src[(size_t)(t-3)*(2*EE)], acc);
            if (t-2 >= 0) acc = fmaf(w1, src[(size_t)(t-2)*(2*EE)], acc);
            if (t-1 >= 0) acc = fmaf(w2, src[(size_t)(t-1)*(2*EE)], acc);
            acc = fmaf(w3, src[(size_t)t*(2*EE)], acc);
        }
        float sg = 1.f / (1.f + __expf(-acc));
        float v = acc * sg;
        __half hv = __float2half_rn(v);
        g_xc[(size_t)tk * EE + e] = hv;
        tx[ly + 8 * i][lx] = hv;
        float z = g_xz[(size_t)tk * (2*EE) + EE + e];
        float zg = 1.f / (1.f + __expf(-z));
        tg[ly + 8 * i][lx] = __float2half_rn(z * zg);
    }
    __syncthreads();
    #pragma unroll
    for (int i = 0; i < 4; i++) {
        int ee = e0 + ly + 8 * i;
        g_xcT[(size_t)ee * NTOK + t0 + lx] = tx[lx][ly + 8 * i];
        g_gT [(size_t)ee * NTOK + t0 + lx] = tg[lx][ly + 8 * i];
    }
}

// ---------------- selective scan (transposed layout, vector prefetch) ------
#define SD 8
__global__ __launch_bounds__(128)
void scan_kernel(const float* __restrict__ A_log,
                 const float* __restrict__ D_skip)
{
    int group = threadIdx.x >> 4;
    int n     = threadIdx.x & 15;
    int ch    = blockIdx.x * 8 + group;   // 0..4095
    int b = ch >> 11;
    int e = ch & (EE - 1);

    float a   = -__expf(A_log[e * NN_ + n]);
    float dsk = D_skip[e];
    float h = 0.f;

    const float*  dtp = g_dtT + (size_t)e * NTOK + b * LL;
    const __half* xp  = g_xcT + (size_t)e * NTOK + b * LL;
    const __half* gp  = g_gT  + (size_t)e * NTOK + b * LL;
    const float*  Bp  = g_bcT + (size_t)n * NTOK + b * LL;
    const float*  Cp  = g_bcT + (size_t)(16 + n) * NTOK + b * LL;
    __half* y0 = g_y + (size_t)b * LL * EE + e;

    float p_dt[2][SD], p_B[2][SD], p_C[2][SD], p_x[2][SD], p_g[2][SD];

#define PREF(BK, TP) do {                                                    \
    int tb = (TP) > (LL - SD) ? (LL - SD) : (TP);                            \
    float4 v0 = *(const float4*)(dtp + tb);                                  \
    float4 v1 = *(const float4*)(dtp + tb + 4);                              \
    p_dt[BK][0]=v0.x; p_dt[BK][1]=v0.y; p_dt[BK][2]=v0.z; p_dt[BK][3]=v0.w;  \
    p_dt[BK][4]=v1.x; p_dt[BK][5]=v1.y; p_dt[BK][6]=v1.z; p_dt[BK][7]=v1.w;  \
    v0 = *(const float4*)(Bp + tb); v1 = *(const float4*)(Bp + tb + 4);      \
    p_B[BK][0]=v0.x; p_B[BK][1]=v0.y; p_B[BK][2]=v0.z; p_B[BK][3]=v0.w;      \
    p_B[BK][4]=v1.x; p_B[BK][5]=v1.y; p_B[BK][6]=v1.z; p_B[BK][7]=v1.w;      \
    v0 = *(const float4*)(Cp + tb); v1 = *(const float4*)(Cp + tb + 4);      \
    p_C[BK][0]=v0.x; p_C[BK][1]=v0.y; p_C[BK][2]=v0.z; p_C[BK][3]=v0.w;      \
    p_C[BK][4]=v1.x; p_C[BK][5]=v1.y; p_C[BK][6]=v1.z; p_C[BK][7]=v1.w;      \
    uint4 u = *(const uint4*)(xp + tb);                                      \
    p_x[BK][0]=h2f_lo(u.x); p_x[BK][1]=h2f_hi(u.x);                          \
    p_x[BK][2]=h2f_lo(u.y); p_x[BK][3]=h2f_hi(u.y);                          \
    p_x[BK][4]=h2f_lo(u.z); p_x[BK][5]=h2f_hi(u.z);                          \
    p_x[BK][6]=h2f_lo(u.w); p_x[BK][7]=h2f_hi(u.w);                          \
    u = *(const uint4*)(gp + tb);                                            \
    p_g[BK][0]=h2f_lo(u.x); p_g[BK][1]=h2f_hi(u.x);                          \
    p_g[BK][2]=h2f_lo(u.y); p_g[BK][3]=h2f_hi(u.y);                          \
    p_g[BK][4]=h2f_lo(u.z); p_g[BK][5]=h2f_hi(u.z);                          \
    p_g[BK][6]=h2f_lo(u.w); p_g[BK][7]=h2f_hi(u.w);                          \
} while (0)

#define COMP(BK, T0) do {                                                    \
    _Pragma("unroll")                                                        \
    for (int j = 0; j < SD; j++) {                                           \
        float dte = p_dt[BK][j];                                             \
        float xe  = p_x[BK][j];                                              \
        float dA  = __expf(dte * a);                                         \
        h = fmaf(h, dA, dte * xe * p_B[BK][j]);                              \
        float p = h * p_C[BK][j];                                            \
        p += __shfl_xor_sync(0xffffffffu, p, 8);                             \
        p += __shfl_xor_sync(0xffffffffu, p, 4);                             \
        p += __shfl_xor_sync(0xffffffffu, p, 2);                             \
        p += __shfl_xor_sync(0xffffffffu, p, 1);                             \
        if (n == 0) {                                                        \
            float y = (p + xe * dsk) * p_g[BK][j];                           \
            y0[(size_t)((T0) + j) * EE] = __float2half_rn(y);                \
        }                                                                    \
    } } while (0)

    PREF(0, 0);
    for (int t0 = 0; t0 < LL; t0 += 2*SD) {
        PREF(1, t0 + SD);
        COMP(0, t0);
        PREF(0, t0 + 2*SD);
        COMP(1, t0 + SD);
    }
#undef PREF
#undef COMP
}

// ---------------- host launch ----------------
extern "C" void kernel_launch(void* const* d_in, const int* in_sizes, int n_in,
                              void* d_out, int out_size)
{
    const int*   tokens   = (const int*)  d_in[0];
    const float* embed    = (const float*)d_in[1];
    const float* norm_w   = (const float*)d_in[2];
    const float* W_in     = (const float*)d_in[3];
    const float* conv_w   = (const float*)d_in[4];
    const float* conv_b   = (const float*)d_in[5];
    const float* W_xproj  = (const float*)d_in[6];
    const float* W_dt     = (const float*)d_in[7];
    const float* dt_bias  = (const float*)d_in[8];
    const float* A_log    = (const float*)d_in[9];
    const float* D_skip   = (const float*)d_in[10];
    const float* W_out    = (const float*)d_in[11];
    const float* final_nw = (const float*)d_in[12];
    const float* lm_head  = (const float*)d_in[13];
    float* out = (float*)d_out;

    float *px, *pxz, *pxpart, *pdtT;
    __half *pxn, *pxc, *pdblh, *pdbll, *py, *pbh, *pbl;
    cudaGetSymbolAddress((void**)&px,    g_x);
    cudaGetSymbolAddress((void**)&pxn,   g_xn);
    cudaGetSymbolAddress((void**)&pxz,   g_xz);
    cudaGetSymbolAddress((void**)&pxc,   g_xc);
    cudaGetSymbolAddress((void**)&pdblh, g_dblh);
    cudaGetSymbolAddress((void**)&pdbll, g_dbll);
    cudaGetSymbolAddress((void**)&pdtT,  g_dtT);
    cudaGetSymbolAddress((void**)&py,    g_y);
    cudaGetSymbolAddress((void**)&pbh,   g_bh);
    cudaGetSymbolAddress((void**)&pbl,   g_bl);
    cudaGetSymbolAddress((void**)&pxpart, g_xpart);

    static bool attr_done = false;
    if (!attr_done) {
        cudaFuncSetAttribute(mmagemm<3,2>, cudaFuncAttributeMaxDynamicSharedMemorySize, 4*24576);
        cudaFuncSetAttribute(mmagemm<0,1>, cudaFuncAttributeMaxDynamicSharedMemorySize, 4*16384);
        cudaFuncSetAttribute(mmagemm<1,1>, cudaFuncAttributeMaxDynamicSharedMemorySize, 4*16384);
        attr_done = true;
    }

    embed_kernel<<<NTOK, 256>>>(tokens, embed);

    for (int l = 0; l < NLAYERS; l++) {
        const float* nw  = norm_w  + (size_t)l * DD;
        const float* win = W_in    + (size_t)l * DD * 2 * EE;
        const float* cw  = conv_w  + (size_t)l * EE * KK;
        const float* cb  = conv_b  + (size_t)l * EE;
        const float* wxp = W_xproj + (size_t)l * EE * 96;
        const float* wdt = W_dt    + (size_t)l * RR * EE;
        const float* dtb = dt_bias + (size_t)l * EE;
        const float* alg = A_log   + (size_t)l * EE * NN_;
        const float* dsk = D_skip  + (size_t)l * EE;
        const float* wo  = W_out   + (size_t)l * EE * DD;

        // 1. rmsnorm -> fp16 xn
        rmsnorm_kernel<<<NTOK, 256>>>(px, nw, pxn);

        // 2. xz = xn @ W_in   (1-term fp16)
        transpose_split_f16<<<dim3(DD/32, (2*EE)/32), dim3(32,8)>>>(win, DD, 2*EE, pbh, nullptr);
        mmagemm<0,1><<<dim3(NTOK/128, (2*EE)/128), 256, 4*16384>>>(
            pxn, pbh, nullptr, pxz, nullptr,
            2*EE, DD, DD, DD, 2*EE, 0);

        // 3. fused conv + silu + gate + transposes
        conv_fused<<<dim3(NTOK/32, EE/32), dim3(32,8)>>>(cw, cb);

        // 4. dbl = xc @ W_xproj  (1-term), split-K x4 + reduce
        transpose_split_f16<<<dim3(EE/32, 128/32), dim3(32,8)>>>(wxp, EE, 96, pbh, nullptr);
        mmagemm<0,1><<<dim3(NTOK/128, 1, 4), 256, 4*16384>>>(
            pxc, pbh, nullptr, pxpart, nullptr,
            96, EE/4, EE, EE, 96, (size_t)NTOK*96);
        reduce_xproj<<<(NTOK*96 + 255)/256, 256>>>();

        // 5. dtT = softplus(W_dt^T @ dbl^T + bias[row]) (2-term) -> [E, NTOK]
        transpose_split_f16<<<dim3(RR/32, EE/32), dim3(32,8)>>>(wdt, RR, EE, pbh, pbl);
        mmagemm<3,2><<<dim3(EE/128, NTOK/128), 256, 4*24576>>>(
            pbh, pdblh, pdbll, pdtT, dtb,
            NTOK, RR, RR, 96, NTOK, 0);

        // 6. selective scan + gate -> fp16 y [t][e]
        scan_kernel<<<(BB*EE)/8, 128>>>(alg, dsk);

        // 7. x += y @ W_out  (1-term fp16)
        transpose_split_f16<<<dim3(EE/32, DD/32), dim3(32,8)>>>(wo, EE, DD, pbh, nullptr);
        mmagemm<1,1><<<dim3(NTOK/128, DD/128), 256, 4*16384>>>(
            py, pbh, nullptr, px, nullptr,
            DD, EE, EE, EE, DD, 0);
    }

    // final rmsnorm -> fp16 xn
    rmsnorm_kernel<<<NTOK, 256>>>(px, final_nw, pxn);

    // logits = xn @ lm_head^T  (1-term fp16); lm_head already [N,K]
    cast_f16<<<(VV*DD/4 + 255)/256, 256>>>((const float4*)lm_head, pbh, VV*DD/4);
    mmagemm<0,1><<<dim3(NTOK/128, VV/128), 256, 4*16384>>>(
        pxn, pbh, nullptr, out, nullptr,
        VV, DD, DD, DD, VV, 0);
}

// round 15
// speedup vs baseline: 1.0593x; 1.0101x over previous
#include <cuda_runtime.h>
#include <cuda_fp16.h>
#include <math.h>
#include <stdint.h>

// Problem dims
#define BB 2
#define LL 2048
#define DD 1024
#define VV 32000
#define NLAYERS 2
#define EE 2048
#define NN_ 16
#define RR 64
#define KK 4
#define NTOK (BB*LL)          // 4096 tokens

// ---------------- scratch (device globals; no allocation allowed) ----------
__device__ float  g_x   [NTOK*DD];      // residual fp32
__device__ __half g_xn  [NTOK*DD];      // rmsnorm out fp16
__device__ __half g_xzh [NTOK*2*EE];    // W_in out fp16
__device__ __half g_xc  [NTOK*EE];      // conv+silu out fp16 [t][e]
__device__ __half g_xcT [EE*NTOK];      // conv+silu out fp16 [e][t]
__device__ __half g_gT  [EE*NTOK];      // silu(z) fp16 [e][t]
__device__ __half g_dblh[NTOK*96];      // xproj out hi fp16 (dt GEMM B)
__device__ __half g_dbll[NTOK*96];      // xproj out lo fp16
__device__ float  g_bcT [32*NTOK];      // B (rows 0..15), C (rows 16..31) [n][tk]
__device__ float  g_xpart[4*NTOK*96];   // xproj split-K partials
__device__ float  g_dtT [EE*NTOK];      // softplus(dt) fp32 [e][tk]
__device__ __half g_y   [NTOK*EE];      // scan out fp16 [t][e]
// dedicated fp16 weight buffers (prepped on side stream)
__device__ __half g_winh[NLAYERS*DD*2*EE];   // [2EE, DD] per layer
__device__ __half g_wxph[NLAYERS*128*EE];    // [128, EE] per layer
__device__ __half g_wdth[NLAYERS*EE*RR];     // [EE, RR] per layer
__device__ __half g_woh [NLAYERS*DD*EE];     // [DD, EE] per layer
__device__ __half g_lmh [VV*DD];             // [VV, DD]

// ======================= helpers ==============================
__device__ __forceinline__ uint32_t smem_u32(const void* p) {
    uint32_t a;
    asm("{ .reg .u64 t; cvta.to.shared.u64 t, %1; cvt.u32.u64 %0, t; }" : "=r"(a) : "l"(p));
    return a;
}
// SW64 swizzle for 64-byte rows (Swizzle<2,4,3>)
#define SWZ64(off) ((off) ^ (((off) >> 3) & 0x30))

__device__ __forceinline__ void ldsm4(uint32_t addr, uint32_t* r) {
    asm volatile("ldmatrix.sync.aligned.m8n8.x4.shared.b16 {%0,%1,%2,%3}, [%4];"
                 : "=r"(r[0]), "=r"(r[1]), "=r"(r[2]), "=r"(r[3]) : "r"(addr));
}
__device__ __forceinline__ void mma_f16(float* d, const uint32_t* a, uint32_t b0, uint32_t b1) {
    asm volatile(
        "mma.sync.aligned.m16n8k16.row.col.f32.f16.f16.f32 "
        "{%0,%1,%2,%3}, {%4,%5,%6,%7}, {%8,%9}, {%0,%1,%2,%3};"
        : "+f"(d[0]), "+f"(d[1]), "+f"(d[2]), "+f"(d[3])
        : "r"(a[0]), "r"(a[1]), "r"(a[2]), "r"(a[3]), "r"(b0), "r"(b1));
}
__device__ __forceinline__ void cp16(uint32_t s, const void* g, bool p) {
    asm volatile("cp.async.cg.shared.global [%0], [%1], 16, %2;"
                 :: "r"(s), "l"(g), "r"(p ? 16 : 0) : "memory");
}
#define CP_COMMIT() asm volatile("cp.async.commit_group;" ::: "memory")
#define CP_WAIT2()  asm volatile("cp.async.wait_group 2;"  ::: "memory")

__device__ __forceinline__ float softplus_f(float v) {
    return (v > 20.f) ? v : log1pf(expf(v));
}
__device__ __forceinline__ float h2f_lo(uint32_t w) {
    return __half2float(__ushort_as_half((unsigned short)(w & 0xFFFFu)));
}
__device__ __forceinline__ float h2f_hi(uint32_t w) {
    return __half2float(__ushort_as_half((unsigned short)(w >> 16)));
}

// ======================= fp16 mma.sync GEMM (R11 config: 4-stage, wait 2) ===
// K-chunk 32, SW64 rows. NT=1: stage 16KB (AH 8K + BH 8K).
//                        NT=2: stage 24KB (AH/BH/BL 8K each).
// A fp16 row-major (lda), Bh/Bl fp16 [N,K] K-major (ldb).
// CTA tile 128x128, 8 warps (4m x 2n, warp tile 32x64).
// grid: (M/128, ceil(N/128), ksplit)
// EPI: 0=store fp32, 1=C+=acc, 2=store fp16, 3=softplus(acc+bias[row])
template<int EPI, int NT>
__global__ __launch_bounds__(256, 2)
void mmagemm(const __half* __restrict__ Ah,
             const __half* __restrict__ Bh, const __half* __restrict__ Bl,
             float* __restrict__ C, const float* __restrict__ bias,
             int N, int K, int lda, int ldb, int ldc, size_t czstride)
{
    constexpr uint32_t STAGE  = (NT == 1) ? 16384u : 24576u;
    constexpr uint32_t OFF_BH = 8192u;
    constexpr uint32_t OFF_BL = 16384u;   // NT2 only

    extern __shared__ __align__(1024) char smem[];
    uint32_t sb = smem_u32(smem);
    const int tid = threadIdx.x;
    const int lane = tid & 31;
    const int wid = tid >> 5;
    const int warp_m = wid >> 1;
    const int warp_n = wid & 1;
    const int bm = blockIdx.x * 128;
    const int bn = blockIdx.y * 128;
    const int zoff = blockIdx.z * K;
    float* Cz = C + (size_t)blockIdx.z * czstride;
    const int nch = K >> 5;

    float acc[2][8][4];
    #pragma unroll
    for (int i = 0; i < 2; i++)
        #pragma unroll
        for (int j = 0; j < 8; j++)
            #pragma unroll
            for (int q = 0; q < 4; q++) acc[i][j][q] = 0.f;

    auto issue = [&](int c, int s) {
        if (c >= nch) return;
        uint32_t st = sb + (uint32_t)s * STAGE;
        const int k0 = zoff + (c << 5);
        const __half* pAh = Ah + (size_t)bm * lda + k0;
        #pragma unroll
        for (int i = 0; i < 2; i++) {           // 128 rows x 4 chunks of 16B
            int idx = i * 256 + tid;
            int row = idx >> 2, c4 = idx & 3;
            uint32_t so = SWZ64((uint32_t)(row * 64 + c4 * 16));
            cp16(st + so, pAh + (size_t)row * lda + c4 * 8, true);
        }
        const __half* pBh = Bh + k0;
        #pragma unroll
        for (int i = 0; i < 2; i++) {
            int idx = i * 256 + tid;
            int row = idx >> 2, c4 = idx & 3;
            bool ok = (bn + row) < N;
            size_t gr = ok ? (size_t)(bn + row) : 0;
            uint32_t so = SWZ64((uint32_t)(row * 64 + c4 * 16));
            cp16(st + OFF_BH + so, pBh + gr * ldb + c4 * 8, ok);
        }
        if (NT == 2) {
            const __half* pBl = Bl + k0;
            #pragma unroll
            for (int i = 0; i < 2; i++) {
                int idx = i * 256 + tid;
                int row = idx >> 2, c4 = idx & 3;
                bool ok = (bn + row) < N;
                size_t gr = ok ? (size_t)(bn + row) : 0;
                uint32_t so = SWZ64((uint32_t)(row * 64 + c4 * 16));
                cp16(st + OFF_BL + so, pBl + gr * ldb + c4 * 8, ok);
            }
        }
    };

    issue(0, 0); CP_COMMIT();
    issue(1, 1); CP_COMMIT();
    issue(2, 2); CP_COMMIT();

    const int arow_l  = warp_m * 32 + (lane & 15);
    const int akoff_l = (lane >> 4) << 4;
    const int brow_l  = warp_n * 64 + (lane & 7) + ((lane >> 4) << 3);
    const int bkoff_l = ((lane >> 3) & 1) << 4;

    for (int c = 0; c < nch; c++) {
        CP_WAIT2();
        __syncthreads();
        uint32_t base = sb + (uint32_t)((c & 3) * STAGE);
        #pragma unroll
        for (int ks = 0; ks < 2; ks++) {
            const int kb = ks * 32;
            uint32_t ah[2][4];
            #pragma unroll
            for (int mi = 0; mi < 2; mi++) {
                uint32_t off = SWZ64((uint32_t)((arow_l + mi * 16) * 64 + kb + akoff_l));
                ldsm4(base + off, ah[mi]);
            }
            #pragma unroll
            for (int nj2 = 0; nj2 < 4; nj2++) {
                uint32_t bh[4], bl[4];
                uint32_t off = SWZ64((uint32_t)((brow_l + nj2 * 16) * 64 + kb + bkoff_l));
                ldsm4(base + OFF_BH + off, bh);
                if (NT == 2) ldsm4(base + OFF_BL + off, bl);
                #pragma unroll
                for (int mi = 0; mi < 2; mi++) {
                    mma_f16(acc[mi][nj2*2+0], ah[mi], bh[0], bh[1]);
                    mma_f16(acc[mi][nj2*2+1], ah[mi], bh[2], bh[3]);
                    if (NT == 2) {
                        mma_f16(acc[mi][nj2*2+0], ah[mi], bl[0], bl[1]);
                        mma_f16(acc[mi][nj2*2+1], ah[mi], bl[2], bl[3]);
                    }
                }
            }
        }
        // writes slot (c+3)&3 == (c-1)&3 — finished by all warps before the
        // sync at the top of this iteration.
        issue(c + 3, (c + 3) & 3);
        CP_COMMIT();
    }

    // ---- epilogue ----
    #pragma unroll
    for (int mi = 0; mi < 2; mi++) {
        #pragma unroll
        for (int nj = 0; nj < 8; nj++) {
            int row = bm + warp_m * 32 + mi * 16 + (lane >> 2);
            int col = bn + warp_n * 64 + nj * 8 + (lane & 3) * 2;
            if (col < N) {
                float* d = acc[mi][nj];
                float2 v0 = make_float2(d[0], d[1]);
                float2 v1 = make_float2(d[2], d[3]);
                if (EPI == 2) {
                    __half* h0p = (__half*)Cz + (size_t)row * ldc + col;
                    __half* h1p = (__half*)Cz + (size_t)(row + 8) * ldc + col;
                    __half2 hv0 = __floats2half2_rn(v0.x, v0.y);
                    __half2 hv1 = __floats2half2_rn(v1.x, v1.y);
                    *(__half2*)h0p = hv0;
                    *(__half2*)h1p = hv1;
                } else {
                    float* p0 = Cz + (size_t)row * ldc + col;
                    float* p1 = Cz + (size_t)(row + 8) * ldc + col;
                    if (EPI == 1) {
                        float2 o0 = *(float2*)p0; v0.x += o0.x; v0.y += o0.y;
                        float2 o1 = *(float2*)p1; v1.x += o1.x; v1.y += o1.y;
                    } else if (EPI == 3) {
                        float br0 = bias[row], br1 = bias[row + 8];
                        v0.x = softplus_f(v0.x + br0); v0.y = softplus_f(v0.y + br0);
                        v1.x = softplus_f(v1.x + br1); v1.y = softplus_f(v1.y + br1);
                    }
                    *(float2*)p0 = v0;
                    *(float2*)p1 = v1;
                }
            }
        }
    }
}

// ============== weight prep: fp32 (K,N) -> fp16 hi (+optional lo) [N,K] =====
__global__ void transpose_split_f16(const float* __restrict__ W, int K, int N,
                                    __half* __restrict__ Bh, __half* __restrict__ Bl)
{
    __shared__ float t[32][33];
    int k0 = blockIdx.x * 32, n0 = blockIdx.y * 32;
    int tx = threadIdx.x, ty = threadIdx.y;   // 32 x 8
    #pragma unroll
    for (int i = 0; i < 4; i++) {
        int k = k0 + ty + 8 * i;
        float v = (n0 + tx < N) ? W[(size_t)k * N + n0 + tx] : 0.f;
        t[ty + 8 * i][tx] = v;
    }
    __syncthreads();
    #pragma unroll
    for (int i = 0; i < 4; i++) {
        int n = n0 + ty + 8 * i;
        int k = k0 + tx;
        float v = t[tx][ty + 8 * i];
        __half h = __float2half_rn(v);
        Bh[(size_t)n * K + k] = h;
        if (Bl) Bl[(size_t)n * K + k] = __float2half_rn(v - __half2float(h));
    }
}

// elementwise fp32 -> fp16 cast (already [N,K] layout): lm_head, hi only
__global__ void cast_f16(const float4* __restrict__ W,
                         __half* __restrict__ Bh, int n4)
{
    int i = blockIdx.x * blockDim.x + threadIdx.x;
    if (i >= n4) return;
    float4 v = W[i];
    __half2 h0 = __floats2half2_rn(v.x, v.y);
    __half2 h1 = __floats2half2_rn(v.z, v.w);
    uint2 hh;
    hh.x = *(uint32_t*)&h0;  hh.y = *(uint32_t*)&h1;
    ((uint2*)Bh)[i] = hh;
}

// ---------------- xproj split-K reduce: dbl hi/lo + transposed B,C ---------
__global__ void reduce_xproj()
{
    int i = blockIdx.x * blockDim.x + threadIdx.x;
    if (i >= NTOK * 96) return;
    float s = g_xpart[i] + g_xpart[i + NTOK*96] + g_xpart[i + 2*NTOK*96] + g_xpart[i + 3*NTOK*96];
    int c = i % 96, t = i / 96;
    if (c < 64) {
        __half h = __float2half_rn(s);
        __half l = __float2half_rn(s - __half2float(h));
        g_dblh[i] = h;
        g_dbll[i] = l;
    } else {
        g_bcT[(size_t)(c - 64) * NTOK + t] = s;
    }
}

// ---------------- embed gather ----------------
__global__ void embed_kernel(const int* __restrict__ tokens,
                             const float* __restrict__ embed)
{
    int t = blockIdx.x;
    int tok = tokens[t];
    const float4* src = (const float4*)(embed + (size_t)tok * DD);
    float4* dst = (float4*)(g_x + (size_t)t * DD);
    for (int i = threadIdx.x; i < DD/4; i += blockDim.x)
        dst[i] = src[i];
}

// ---------------- rmsnorm (writes fp16) ----------------
__global__ void rmsnorm_kernel(const float* __restrict__ x,
                               const float* __restrict__ w,
                               __half* __restrict__ o)
{
    int t = blockIdx.x;
    const float4* xr = (const float4*)(x + (size_t)t * DD);
    const float4* wr = (const float4*)w;

    float s = 0.f;
    for (int i = threadIdx.x; i < DD/4; i += blockDim.x) {
        float4 v = xr[i];
        s += v.x*v.x + v.y*v.y + v.z*v.z + v.w*v.w;
    }
    __shared__ float red[8];
    for (int m = 16; m > 0; m >>= 1) s += __shfl_xor_sync(0xffffffffu, s, m);
    if ((threadIdx.x & 31) == 0) red[threadIdx.x >> 5] = s;
    __syncthreads();
    float tot = 0.f;
    if (threadIdx.x < 8) tot = red[threadIdx.x];
    for (int m = 4; m > 0; m >>= 1) tot += __shfl_xor_sync(0xffffffffu, tot, m);
    __shared__ float inv_s;
    if (threadIdx.x == 0) inv_s = rsqrtf(tot / (float)DD + 1e-5f);
    __syncthreads();
    float inv = inv_s;

    for (int i = threadIdx.x; i < DD/4; i += blockDim.x) {
        float4 v = xr[i];
        float4 wv = wr[i];
        __half2 h0 = __floats2half2_rn(v.x * wv.x * inv, v.y * wv.y * inv);
        __half2 h1 = __floats2half2_rn(v.z * wv.z * inv, v.w * wv.w * inv);
        uint2 hh;
        hh.x = *(uint32_t*)&h0; hh.y = *(uint32_t*)&h1;
        *(uint2*)(o + (size_t)t * DD + i * 4) = hh;
    }
}

// ------ fused causal conv (K=4) + silu + gate + dual-layout transpose ------
// reads fp16 xz
__global__ void conv_fused(const float* __restrict__ conv_w,
                           const float* __restrict__ conv_b)
{
    __shared__ __half tx[32][33];
    __shared__ __half tg[32][33];
    int t0 = blockIdx.x * 32, e0 = blockIdx.y * 32;
    int lx = threadIdx.x, ly = threadIdx.y;
    int e = e0 + lx;
    float w0 = conv_w[e*KK+0], w1 = conv_w[e*KK+1], w2 = conv_w[e*KK+2], w3 = conv_w[e*KK+3];
    float cb = conv_b[e];
    #pragma unroll
    for (int i = 0; i < 4; i++) {
        int tk = t0 + ly + 8 * i;
        int t = tk % LL;
        const __half* src = g_xzh + (size_t)(tk - t) * (2*EE) + e;
        float acc = cb;
        if (t >= 3) {
            acc = fmaf(w0, __half2float(src[(size_t)(t-3)*(2*EE)]), acc);
            acc = fmaf(w1, __half2float(src[(size_t)(t-2)*(2*EE)]), acc);
            acc = fmaf(w2, __half2float(src[(size_t)(t-1)*(2*EE)]), acc);
            acc = fmaf(w3, __half2float(src[(size_t)(t  )*(2*EE)]), acc);
        } else {
            if (t-3 >= 0) acc = fmaf(w0, __half2float(src[(size_t)(t-3)*(2*EE)]), acc);
            if (t-2 >= 0) acc = fmaf(w1, __half2float(src[(size_t)(t-2)*(2*EE)]), acc);
            if (t-1 >= 0) acc = fmaf(w2, __half2float(src[(size_t)(t-1)*(2*EE)]), acc);
            acc = fmaf(w3, __half2float(src[(size_t)t*(2*EE)]), acc);
        }
        float sg = 1.f / (1.f + __expf(-acc));
        float v = acc * sg;
        __half hv = __float2half_rn(v);
        g_xc[(size_t)tk * EE + e] = hv;
        tx[ly + 8 * i][lx] = hv;
        float z = __half2float(g_xzh[(size_t)tk * (2*EE) + EE + e]);
        float zg = 1.f / (1.f + __expf(-z));
        tg[ly + 8 * i][lx] = __float2half_rn(z * zg);
    }
    __syncthreads();
    #pragma unroll
    for (int i = 0; i < 4; i++) {
        int ee = e0 + ly + 8 * i;
        g_xcT[(size_t)ee * NTOK + t0 + lx] = tx[lx][ly + 8 * i];
        g_gT [(size_t)ee * NTOK + t0 + lx] = tg[lx][ly + 8 * i];
    }
}

// ---------------- selective scan (transposed layout, vector prefetch) ------
#define SD 8
__global__ __launch_bounds__(128)
void scan_kernel(const float* __restrict__ A_log,
                 const float* __restrict__ D_skip)
{
    int group = threadIdx.x >> 4;
    int n     = threadIdx.x & 15;
    int ch    = blockIdx.x * 8 + group;   // 0..4095
    int b = ch >> 11;
    int e = ch & (EE - 1);

    float a   = -__expf(A_log[e * NN_ + n]);
    float dsk = D_skip[e];
    float h = 0.f;

    const float*  dtp = g_dtT + (size_t)e * NTOK + b * LL;
    const __half* xp  = g_xcT + (size_t)e * NTOK + b * LL;
    const __half* gp  = g_gT  + (size_t)e * NTOK + b * LL;
    const float*  Bp  = g_bcT + (size_t)n * NTOK + b * LL;
    const float*  Cp  = g_bcT + (size_t)(16 + n) * NTOK + b * LL;
    __half* y0 = g_y + (size_t)b * LL * EE + e;

    float p_dt[2][SD], p_B[2][SD], p_C[2][SD], p_x[2][SD], p_g[2][SD];

#define PREF(BK, TP) do {                                                    \
    int tb = (TP) > (LL - SD) ? (LL - SD) : (TP);                            \
    float4 v0 = *(const float4*)(dtp + tb);                                  \
    float4 v1 = *(const float4*)(dtp + tb + 4);                              \
    p_dt[BK][0]=v0.x; p_dt[BK][1]=v0.y; p_dt[BK][2]=v0.z; p_dt[BK][3]=v0.w;  \
    p_dt[BK][4]=v1.x; p_dt[BK][5]=v1.y; p_dt[BK][6]=v1.z; p_dt[BK][7]=v1.w;  \
    v0 = *(const float4*)(Bp + tb); v1 = *(const float4*)(Bp + tb + 4);      \
    p_B[BK][0]=v0.x; p_B[BK][1]=v0.y; p_B[BK][2]=v0.z; p_B[BK][3]=v0.w;      \
    p_B[BK][4]=v1.x; p_B[BK][5]=v1.y; p_B[BK][6]=v1.z; p_B[BK][7]=v1.w;      \
    v0 = *(const float4*)(Cp + tb); v1 = *(const float4*)(Cp + tb + 4);      \
    p_C[BK][0]=v0.x; p_C[BK][1]=v0.y; p_C[BK][2]=v0.z; p_C[BK][3]=v0.w;      \
    p_C[BK][4]=v1.x; p_C[BK][5]=v1.y; p_C[BK][6]=v1.z; p_C[BK][7]=v1.w;      \
    uint4 u = *(const uint4*)(xp + tb);                                      \
    p_x[BK][0]=h2f_lo(u.x); p_x[BK][1]=h2f_hi(u.x);                          \
    p_x[BK][2]=h2f_lo(u.y); p_x[BK][3]=h2f_hi(u.y);                          \
    p_x[BK][4]=h2f_lo(u.z); p_x[BK][5]=h2f_hi(u.z);                          \
    p_x[BK][6]=h2f_lo(u.w); p_x[BK][7]=h2f_hi(u.w);                          \
    u = *(const uint4*)(gp + tb);                                            \
    p_g[BK][0]=h2f_lo(u.x); p_g[BK][1]=h2f_hi(u.x);                          \
    p_g[BK][2]=h2f_lo(u.y); p_g[BK][3]=h2f_hi(u.y);                          \
    p_g[BK][4]=h2f_lo(u.z); p_g[BK][5]=h2f_hi(u.z);                          \
    p_g[BK][6]=h2f_lo(u.w); p_g[BK][7]=h2f_hi(u.w);                          \
} while (0)

#define COMP(BK, T0) do {                                                    \
    _Pragma("unroll")                                                        \
    for (int j = 0; j < SD; j++) {                                           \
        float dte = p_dt[BK][j];                                             \
        float xe  = p_x[BK][j];                                              \
        float dA  = __expf(dte * a);                                         \
        h = fmaf(h, dA, dte * xe * p_B[BK][j]);                              \
        float p = h * p_C[BK][j];                                            \
        p += __shfl_xor_sync(0xffffffffu, p, 8);                             \
        p += __shfl_xor_sync(0xffffffffu, p, 4);                             \
        p += __shfl_xor_sync(0xffffffffu, p, 2);                             \
        p += __shfl_xor_sync(0xffffffffu, p, 1);                             \
        if (n == 0) {                                                        \
            float y = (p + xe * dsk) * p_g[BK][j];                           \
            y0[(size_t)((T0) + j) * EE] = __float2half_rn(y);                \
        }                                                                    \
    } } while (0)

    PREF(0, 0);
    for (int t0 = 0; t0 < LL; t0 += 2*SD) {
        PREF(1, t0 + SD);
        COMP(0, t0);
        PREF(0, t0 + 2*SD);
        COMP(1, t0 + SD);
    }
#undef PREF
#undef COMP
}

// ---------------- host launch ----------------
extern "C" void kernel_launch(void* const* d_in, const int* in_sizes, int n_in,
                              void* d_out, int out_size)
{
    const int*   tokens   = (const int*)  d_in[0];
    const float* embed    = (const float*)d_in[1];
    const float* norm_w   = (const float*)d_in[2];
    const float* W_in     = (const float*)d_in[3];
    const float* conv_w   = (const float*)d_in[4];
    const float* conv_b   = (const float*)d_in[5];
    const float* W_xproj  = (const float*)d_in[6];
    const float* W_dt     = (const float*)d_in[7];
    const float* dt_bias  = (const float*)d_in[8];
    const float* A_log    = (const float*)d_in[9];
    const float* D_skip   = (const float*)d_in[10];
    const float* W_out    = (const float*)d_in[11];
    const float* final_nw = (const float*)d_in[12];
    const float* lm_head  = (const float*)d_in[13];
    float* out = (float*)d_out;

    float *px, *pxpart, *pdtT;
    __half *pxn, *pxzh, *pxc, *pdblh, *pdbll, *py;
    __half *pwinh, *pwxph, *pwdth, *pwoh, *plmh;
    cudaGetSymbolAddress((void**)&px,    g_x);
    cudaGetSymbolAddress((void**)&pxn,   g_xn);
    cudaGetSymbolAddress((void**)&pxzh,  g_xzh);
    cudaGetSymbolAddress((void**)&pxc,   g_xc);
    cudaGetSymbolAddress((void**)&pdblh, g_dblh);
    cudaGetSymbolAddress((void**)&pdbll, g_dbll);
    cudaGetSymbolAddress((void**)&pdtT,  g_dtT);
    cudaGetSymbolAddress((void**)&py,    g_y);
    cudaGetSymbolAddress((void**)&pxpart, g_xpart);
    cudaGetSymbolAddress((void**)&pwinh, g_winh);
    cudaGetSymbolAddress((void**)&pwxph, g_wxph);
    cudaGetSymbolAddress((void**)&pwdth, g_wdth);
    cudaGetSymbolAddress((void**)&pwoh,  g_woh);
    cudaGetSymbolAddress((void**)&plmh,  g_lmh);

    static bool init_done = false;
    static cudaStream_t s2;
    static cudaEvent_t evFork;
    static cudaEvent_t evW[NLAYERS][4];   // win, wxp, wdt, wo
    static cudaEvent_t evLm;
    if (!init_done) {
        cudaFuncSetAttribute(mmagemm<3,2>, cudaFuncAttributeMaxDynamicSharedMemorySize, 4*24576);
        cudaFuncSetAttribute(mmagemm<0,1>, cudaFuncAttributeMaxDynamicSharedMemorySize, 4*16384);
        cudaFuncSetAttribute(mmagemm<1,1>, cudaFuncAttributeMaxDynamicSharedMemorySize, 4*16384);
        cudaFuncSetAttribute(mmagemm<2,1>, cudaFuncAttributeMaxDynamicSharedMemorySize, 4*16384);
        cudaStreamCreateWithFlags(&s2, cudaStreamNonBlocking);
        cudaEventCreateWithFlags(&evFork, cudaEventDisableTiming);
        for (int l = 0; l < NLAYERS; l++)
            for (int i = 0; i < 4; i++)
                cudaEventCreateWithFlags(&evW[l][i], cudaEventDisableTiming);
        cudaEventCreateWithFlags(&evLm, cudaEventDisableTiming);
        init_done = true;
    }

    // ---- fork side stream: all weight preps (depend only on inputs) ----
    cudaEventRecord(evFork, 0);
    cudaStreamWaitEvent(s2, evFork, 0);
    for (int l = 0; l < NLAYERS; l++) {
        const float* win = W_in    + (size_t)l * DD * 2 * EE;
        const float* wxp = W_xproj + (size_t)l * EE * 96;
        const float* wdt = W_dt    + (size_t)l * RR * EE;
        const float* wo  = W_out   + (size_t)l * EE * DD;
        transpose_split_f16<<<dim3(DD/32, (2*EE)/32), dim3(32,8), 0, s2>>>(
            win, DD, 2*EE, pwinh + (size_t)l * DD * 2 * EE, nullptr);
        cudaEventRecord(evW[l][0], s2);
        transpose_split_f16<<<dim3(EE/32, 128/32), dim3(32,8), 0, s2>>>(
            wxp, EE, 96, pwxph + (size_t)l * 128 * EE, nullptr);
        cudaEventRecord(evW[l][1], s2);
        transpose_split_f16<<<dim3(RR/32, EE/32), dim3(32,8), 0, s2>>>(
            wdt, RR, EE, pwdth + (size_t)l * EE * RR, nullptr);
        cudaEventRecord(evW[l][2], s2);
        transpose_split_f16<<<dim3(EE/32, DD/32), dim3(32,8), 0, s2>>>(
            wo, EE, DD, pwoh + (size_t)l * DD * EE, nullptr);
        cudaEventRecord(evW[l][3], s2);
    }
    cast_f16<<<(VV*DD/4 + 255)/256, 256, 0, s2>>>((const float4*)lm_head, plmh, VV*DD/4);
    cudaEventRecord(evLm, s2);

    // ---- main stream ----
    embed_kernel<<<NTOK, 256>>>(tokens, embed);

    for (int l = 0; l < NLAYERS; l++) {
        const float* nw  = norm_w  + (size_t)l * DD;
        const float* cw  = conv_w  + (size_t)l * EE * KK;
        const float* cb  = conv_b  + (size_t)l * EE;
        const float* dtb = dt_bias + (size_t)l * EE;
        const float* alg = A_log   + (size_t)l * EE * NN_;
        const float* dsk = D_skip  + (size_t)l * EE;
        __half* winh = pwinh + (size_t)l * DD * 2 * EE;
        __half* wxph = pwxph + (size_t)l * 128 * EE;
        __half* wdth = pwdth + (size_t)l * EE * RR;
        __half* woh  = pwoh  + (size_t)l * DD * EE;

        // 1. rmsnorm -> fp16 xn
        rmsnorm_kernel<<<NTOK, 256>>>(px, nw, pxn);

        // 2. xz = xn @ W_in   (1-term fp16, fp16 out)
        cudaStreamWaitEvent(0, evW[l][0], 0);
        mmagemm<2,1><<<dim3(NTOK/128, (2*EE)/128), 256, 4*16384>>>(
            pxn, winh, nullptr, (float*)pxzh, nullptr,
            2*EE, DD, DD, DD, 2*EE, 0);

        // 3. fused conv + silu + gate + transposes
        conv_fused<<<dim3(NTOK/32, EE/32), dim3(32,8)>>>(cw, cb);

        // 4. dbl = xc @ W_xproj  (1-term), split-K x4 + reduce
        cudaStreamWaitEvent(0, evW[l][1], 0);
        mmagemm<0,1><<<dim3(NTOK/128, 1, 4), 256, 4*16384>>>(
            pxc, wxph, nullptr, pxpart, nullptr,
            96, EE/4, EE, EE, 96, (size_t)NTOK*96);
        reduce_xproj<<<(NTOK*96 + 255)/256, 256>>>();

        // 5. dtT = softplus(W_dt^T @ dbl^T + bias[row]) (2-term) -> [E, NTOK]
        cudaStreamWaitEvent(0, evW[l][2], 0);
        mmagemm<3,2><<<dim3(EE/128, NTOK/128), 256, 4*24576>>>(
            wdth, pdblh, pdbll, pdtT, dtb,
            NTOK, RR, RR, 96, NTOK, 0);

        // 6. selective scan + gate -> fp16 y [t][e]
        scan_kernel<<<(BB*EE)/8, 128>>>(alg, dsk);

        // 7. x += y @ W_out  (1-term fp16)
        cudaStreamWaitEvent(0, evW[l][3], 0);
        mmagemm<1,1><<<dim3(NTOK/128, DD/128), 256, 4*16384>>>(
            py, woh, nullptr, px, nullptr,
            DD, EE, EE, EE, DD, 0);
    }

    // final rmsnorm -> fp16 xn
    rmsnorm_kernel<<<NTOK, 256>>>(px, final_nw, pxn);

    // logits = xn @ lm_head^T  (1-term fp16)
    cudaStreamWaitEvent(0, evLm, 0);
    mmagemm<0,1><<<dim3(NTOK/128, VV/128), 256, 4*16384>>>(
        pxn, plmh, nullptr, out, nullptr,
        VV, DD, DD, DD, VV, 0);
}